// round 4
// baseline (speedup 1.0000x reference)
#include <cuda_runtime.h>
#include <cuda_bf16.h>
#include <cstdint>

// Problem constants
#define MCC    10
#define INC    16
#define OUTC   32
#define HW_IN  128
#define HW_OUT 64
#define KTOT   144          // 3*3*16
#define NTOT   320

// Tiles: CTA = 160 channels (MMA-M) x 128 pixels (MMA-N), full K=144
#define THREADS 256
#define CH_TILE 160
#define PX_TILE 128
#define AK      152         // padded K (bf16 elems); row stride 304 B = 19*16B
#define AKB     304

#define OFF_XHI 0
#define OFF_XLO (PX_TILE * AKB)                  // 38912
#define OFF_WHI (2 * PX_TILE * AKB)              // 77824
#define OFF_WLO (2 * PX_TILE * AKB + CH_TILE * AKB)  // 126464
#define SMEM_BYTES (2 * PX_TILE * AKB + 2 * CH_TILE * AKB)  // 175104

__device__ float d_W[KTOT * NTOT];   // [k][n], n = mc*32 + oc

__device__ __forceinline__ uint32_t smem_u32(const void* p) {
    uint32_t a;
    asm("{ .reg .u64 t; cvta.to.shared.u64 t, %1; cvt.u32.u64 %0, t; }" : "=r"(a) : "l"(p));
    return a;
}

__device__ __forceinline__ void ldmx4(uint32_t addr, uint32_t &r0, uint32_t &r1,
                                      uint32_t &r2, uint32_t &r3) {
    asm volatile("ldmatrix.sync.aligned.m8n8.x4.shared.b16 {%0,%1,%2,%3}, [%4];"
                 : "=r"(r0), "=r"(r1), "=r"(r2), "=r"(r3) : "r"(addr));
}

__device__ __forceinline__ void mma16816(float* d, const uint32_t* a, const uint32_t* bb) {
    asm volatile(
        "mma.sync.aligned.m16n8k16.row.col.f32.bf16.bf16.f32 "
        "{%0,%1,%2,%3}, {%4,%5,%6,%7}, {%8,%9}, {%0,%1,%2,%3};"
        : "+f"(d[0]), "+f"(d[1]), "+f"(d[2]), "+f"(d[3])
        : "r"(a[0]), "r"(a[1]), "r"(a[2]), "r"(a[3]), "r"(bb[0]), "r"(bb[1]));
}

__device__ __forceinline__ void fast_sincos(float v, float &s, float &c) {
    float t = rintf(v * 0.15915494309189535f);
    float r = fmaf(t, -6.2831855f, v);
    r = fmaf(t, 1.7484555e-7f, r);
    s = __sinf(r);
    c = __cosf(r);
}

__global__ void prep_w_kernel(const float* __restrict__ mean,
                              const float* __restrict__ ls,
                              const float* __restrict__ eps) {
    int i = blockIdx.x * 256 + threadIdx.x;     // over [mc][d][oc] = 46080
    if (i >= MCC * KTOT * OUTC) return;
    int oc = i & 31;
    int t  = i >> 5;
    int d  = t % KTOT;
    int mc = t / KTOT;
    float w = fmaf(eps[i], expf(0.5f * ls[d * OUTC + oc]), mean[d * OUTC + oc]);
    d_W[d * NTOT + mc * OUTC + oc] = w;
}

__global__ void __launch_bounds__(THREADS)
conv_rff_hmma_kernel(const float* __restrict__ x,
                     const float* __restrict__ theta,
                     float* __restrict__ out) {
    extern __shared__ char sm[];
    const uint32_t smb = smem_u32(sm);

    const int tid   = threadIdx.x;
    const int wid   = tid >> 5;
    const int lane  = tid & 31;
    const int ntile = blockIdx.x;   // 0..1 (160-channel half)
    const int rg    = blockIdx.y;   // 0..31 (output-row pair)
    const int b     = blockIdx.z;   // 0..7

    // ---- Stage X (im2col pixels, bf16 hi/lo): X[px][k] ----
    {
        __nv_bfloat16* Xh = (__nv_bfloat16*)(sm + OFF_XHI);
        __nv_bfloat16* Xl = (__nv_bfloat16*)(sm + OFF_XLO);
        const float* xb = x + (size_t)b * INC * HW_IN * HW_IN;
        for (int i = tid; i < PX_TILE * KTOT; i += THREADS) {   // 72 iters
            int m = i / KTOT;
            int k = i - m * KTOT;
            int kh  = k / 48;
            int rem = k - kh * 48;
            int kw  = rem >> 4;
            int c   = rem & 15;
            int oyp = m >> 6;
            int ox  = m & 63;
            int iy  = 4 * rg + 2 * oyp + kh - 1;
            int ix  = 2 * ox + kw - 1;
            float v = 0.f;
            if ((unsigned)iy < (unsigned)HW_IN && (unsigned)ix < (unsigned)HW_IN)
                v = xb[(c * HW_IN + iy) * HW_IN + ix];
            __nv_bfloat16 hi = __float2bfloat16_rn(v);
            __nv_bfloat16 lo = __float2bfloat16_rn(v - __bfloat162float(hi));
            *(__nv_bfloat16*)((char*)Xh + m * AKB + k * 2) = hi;
            *(__nv_bfloat16*)((char*)Xl + m * AKB + k * 2) = lo;
        }
    }
    // ---- Stage W (weights, bf16 hi/lo): W[ch][k] ----
    {
        __nv_bfloat16* Wh = (__nv_bfloat16*)(sm + OFF_WHI);
        __nv_bfloat16* Wl = (__nv_bfloat16*)(sm + OFF_WLO);
        const float* Wg = d_W + ntile * CH_TILE;
        for (int i = tid; i < CH_TILE * KTOT; i += THREADS) {   // 90 iters
            int k = i / CH_TILE;
            int n = i - k * CH_TILE;
            float w = Wg[k * NTOT + n];
            __nv_bfloat16 hi = __float2bfloat16_rn(w);
            __nv_bfloat16 lo = __float2bfloat16_rn(w - __bfloat162float(hi));
            *(__nv_bfloat16*)((char*)Wh + n * AKB + k * 2) = hi;
            *(__nv_bfloat16*)((char*)Wl + n * AKB + k * 2) = lo;
        }
    }
    __syncthreads();

    // ---- Mainloop: warp tile 80ch x 32px; 3 splits x 9 k-chunks ----
    const int chbase = (wid >> 2) * 80;   // 0 or 80
    const int pxbase = (wid & 3) * 32;    // 0,32,64,96

    // ldmatrix lane-address offsets (bytes)
    const uint32_t a_off = (uint32_t)((lane & 15) * AKB + (lane >> 4) * 16);
    const uint32_t b_off = (uint32_t)(((lane >> 4) * 8 + (lane & 7)) * AKB +
                                      ((lane >> 3) & 1) * 16);

    float acc[5][4][4];
    #pragma unroll
    for (int mi = 0; mi < 5; ++mi)
        #pragma unroll
        for (int ni = 0; ni < 4; ++ni)
            #pragma unroll
            for (int c = 0; c < 4; ++c)
                acc[mi][ni][c] = 0.f;

    #pragma unroll
    for (int s = 0; s < 3; ++s) {
        // s0: Whi*Xhi, s1: Whi*Xlo, s2: Wlo*Xhi
        const uint32_t wbase = smb + ((s == 2) ? OFF_WLO : OFF_WHI) + chbase * AKB + a_off;
        const uint32_t xbase = smb + ((s == 1) ? OFF_XLO : OFF_XHI) + pxbase * AKB + b_off;
        #pragma unroll
        for (int kc = 0; kc < 9; ++kc) {
            const uint32_t kb = kc * 32;   // k0*2 bytes
            uint32_t bfr[4][2];
            #pragma unroll
            for (int g = 0; g < 2; ++g) {
                uint32_t r0, r1, r2, r3;
                ldmx4(xbase + g * (16 * AKB) + kb, r0, r1, r2, r3);
                bfr[2*g][0]   = r0; bfr[2*g][1]   = r1;
                bfr[2*g+1][0] = r2; bfr[2*g+1][1] = r3;
            }
            #pragma unroll
            for (int mi = 0; mi < 5; ++mi) {
                uint32_t a[4];
                ldmx4(wbase + mi * (16 * AKB) + kb, a[0], a[1], a[2], a[3]);
                #pragma unroll
                for (int ni = 0; ni < 4; ++ni)
                    mma16816(acc[mi][ni], a, bfr[ni]);
            }
        }
    }

    // ---- Epilogue: scale*{cos,sin}, float2 stores ----
    const float scale = expf(0.5f * theta[0]) * 0.0027621358640644f; // 1/sqrt(32*64*64)
    const int l2 = lane >> 2;
    const int l3 = lane & 3;

    #pragma unroll
    for (int mi = 0; mi < 5; ++mi) {
        #pragma unroll
        for (int msub = 0; msub < 2; ++msub) {
            int ch  = chbase + mi * 16 + msub * 8 + l2;
            int ngl = ntile * CH_TILE + ch;              // global channel [0,320)
            int chan = (ngl >> 5) * 64 + (ngl & 31);     // mc*64 + oc
            float* basec = out + ((size_t)(b * (MCC * 2 * OUTC) + chan)) * (HW_OUT * HW_OUT);
            float* bases = basec + (size_t)OUTC * HW_OUT * HW_OUT;
            #pragma unroll
            for (int ni = 0; ni < 4; ++ni) {
                int px = pxbase + ni * 8 + 2 * l3;
                int oy = 2 * rg + (px >> 6);
                int ox = px & 63;
                float v0 = acc[mi][ni][msub * 2 + 0];
                float v1 = acc[mi][ni][msub * 2 + 1];
                float s0, c0, s1, c1;
                fast_sincos(v0, s0, c0);
                fast_sincos(v1, s1, c1);
                *(float2*)(basec + oy * HW_OUT + ox) = make_float2(scale * c0, scale * c1);
                *(float2*)(bases + oy * HW_OUT + ox) = make_float2(scale * s0, scale * s1);
            }
        }
    }
}

extern "C" void kernel_launch(void* const* d_in, const int* in_sizes, int n_in,
                              void* d_out, int out_size) {
    const float* x     = (const float*)d_in[0];
    const float* theta = (const float*)d_in[1];
    const float* mean  = (const float*)d_in[2];
    const float* ls    = (const float*)d_in[3];
    const float* eps   = (const float*)d_in[4];
    float* out = (float*)d_out;

    prep_w_kernel<<<(MCC * KTOT * OUTC + 255) / 256, 256>>>(mean, ls, eps);

    cudaFuncSetAttribute(conv_rff_hmma_kernel,
                         cudaFuncAttributeMaxDynamicSharedMemorySize, SMEM_BYTES);
    dim3 grid(2, 32, 8);   // n-half, row-pair, batch
    conv_rff_hmma_kernel<<<grid, THREADS, SMEM_BYTES>>>(x, theta, out);
}